// round 4
// baseline (speedup 1.0000x reference)
#include <cuda_runtime.h>
#include <stdint.h>

#define NROWS   (64*2048)
#define DIM     64
#define KC      1024
#define QELEMS  (NROWS*DIM)

#define BT      128            // threads/block (4 warps)
#define BROWS   128            // rows per block (32 per warp)
#define CK      128            // codes per chunk
#define NCK     (KC/CK)        // 8
#define BSTRIDE 68             // padded floats per code row in smem (bank-conflict-free)
#define BUFU    (CK*BSTRIDE)   // uints per B buffer
#define CAP     8
#define EPS     1.5e-3f

// dynamic smem layout (uints/floats)
#define SM_B    0                       // uint sB[2][BUFU]  (tf32 bits)
#define SM_SS   (2*BUFU*4)              // float ss[2][CK]
#define SM_CTH  (SM_SS + 2*CK*4)        // float cth[BROWS]
#define SM_RED  (SM_CTH + BROWS*4)      // double sred[4]
#define SMEMSZ  (SM_RED + 64)

__device__ double g_loss_acc;

static __device__ __forceinline__ uint32_t tf32(float f){
    uint32_t r;
    asm("cvt.rna.tf32.f32 %0, %1;" : "=r"(r) : "f"(f));
    return r;
}
static __device__ __forceinline__ void mma8(float c[4], const uint32_t a[4],
                                            uint32_t b0, uint32_t b1){
    asm volatile("mma.sync.aligned.m16n8k8.row.col.f32.tf32.tf32.f32 "
        "{%0,%1,%2,%3}, {%4,%5,%6,%7}, {%8,%9}, {%0,%1,%2,%3};"
        : "+f"(c[0]),"+f"(c[1]),"+f"(c[2]),"+f"(c[3])
        : "r"(a[0]),"r"(a[1]),"r"(a[2]),"r"(a[3]), "r"(b0),"r"(b1));
}

__global__ void vq_zero_kernel(){ g_loss_acc = 0.0; }

// exact fp32 distance — replicates the round-1 (reference-matching) rounding order
static __device__ __forceinline__ float exact_dist(const float* __restrict__ wrow,
                                                   const float* __restrict__ xv, float cth){
    float ww[64];
    const float4* w4 = reinterpret_cast<const float4*>(wrow);
    #pragma unroll
    for (int i=0;i<16;i++){
        float4 v = w4[i];
        ww[4*i+0]=v.x; ww[4*i+1]=v.y; ww[4*i+2]=v.z; ww[4*i+3]=v.w;
    }
    float ss = 0.f;
    #pragma unroll
    for (int d=0; d<64; d++) ss = __fadd_rn(ss, __fmul_rn(ww[d], ww[d]));
    float s0=0.f, s1=0.f, s2=0.f, s3=0.f;
    #pragma unroll
    for (int d=0; d<64; d+=4){
        s0 = __fmaf_rn(xv[d+0], ww[d+0], s0);
        s1 = __fmaf_rn(xv[d+1], ww[d+1], s1);
        s2 = __fmaf_rn(xv[d+2], ww[d+2], s2);
        s3 = __fmaf_rn(xv[d+3], ww[d+3], s3);
    }
    float m = __fadd_rn(__fadd_rn(s0,s1), __fadd_rn(s2,s3));
    return __fsub_rn(__fadd_rn(cth, ss), __fmul_rn(2.0f, m));
}

__global__ __launch_bounds__(BT) void vq_main(const float* __restrict__ x,
                                              const float* __restrict__ w,
                                              float* __restrict__ out)
{
    extern __shared__ char smem[];
    uint32_t* sB   = reinterpret_cast<uint32_t*>(smem + SM_B);
    float*    ssb  = reinterpret_cast<float*>(smem + SM_SS);
    float*    cths = reinterpret_cast<float*>(smem + SM_CTH);
    double*   sred = reinterpret_cast<double*>(smem + SM_RED);

    const int tid  = threadIdx.x;
    const int warp = tid >> 5;
    const int lane = tid & 31;
    const int g    = lane >> 2;   // group id 0..7
    const int q    = lane & 3;    // thread-in-group 0..3
    const int blk  = blockIdx.x;
    const int wrow = warp * 32;   // warp's first row within block
    const size_t rowbase = (size_t)blk * BROWS;

    // ---- approx ||x||^2 per row (cooperative; approx ok, recheck recomputes exactly) ----
    {
        const float4* xr = reinterpret_cast<const float4*>(x + (rowbase + tid)*DIM);
        float s0=0.f,s1=0.f,s2=0.f,s3=0.f;
        #pragma unroll
        for (int i=0;i<16;i++){
            float4 v = xr[i];
            s0 = __fmaf_rn(v.x,v.x,s0); s1 = __fmaf_rn(v.y,v.y,s1);
            s2 = __fmaf_rn(v.z,v.z,s2); s3 = __fmaf_rn(v.w,v.w,s3);
        }
        cths[tid] = __fadd_rn(__fadd_rn(s0,s1), __fadd_rn(s2,s3));
    }

    // ---- A fragments (2 row-tiles x 8 k-steps x 4 regs), tf32 ----
    uint32_t atf[2][8][4];
    {
        const float* xb = x + (rowbase + wrow)*DIM;
        #pragma unroll
        for (int rt=0; rt<2; rt++){
            #pragma unroll
            for (int k=0; k<8; k++){
                int r0 = rt*16 + g;
                int c0 = k*8 + q;
                atf[rt][k][0] = tf32(xb[(r0  )*DIM + c0    ]);
                atf[rt][k][1] = tf32(xb[(r0+8)*DIM + c0    ]);
                atf[rt][k][2] = tf32(xb[(r0  )*DIM + c0 + 4]);
                atf[rt][k][3] = tf32(xb[(r0+8)*DIM + c0 + 4]);
            }
        }
    }

    // ---- B chunk loader (codes [cb,cb+CK) -> buffer bi, tf32 + approx norms) ----
    auto loadB = [&](int cb, int bi){
        const float4* wg = reinterpret_cast<const float4*>(w + (size_t)cb*DIM);
        #pragma unroll
        for (int i=0;i<16;i++){
            int f4 = tid + i*BT;
            float4 v = wg[f4];
            int code = f4 >> 4;
            int dim  = (f4 & 15) * 4;
            uint32_t* dst = sB + bi*BUFU + code*BSTRIDE + dim;
            dst[0]=tf32(v.x); dst[1]=tf32(v.y); dst[2]=tf32(v.z); dst[3]=tf32(v.w);
        }
        {   // approx per-code norm (fp32)
            const float4* wr = reinterpret_cast<const float4*>(w + (size_t)(cb + tid)*DIM);
            float s0=0.f,s1=0.f,s2=0.f,s3=0.f;
            #pragma unroll
            for (int i=0;i<16;i++){
                float4 v = wr[i];
                s0 = __fmaf_rn(v.x,v.x,s0); s1 = __fmaf_rn(v.y,v.y,s1);
                s2 = __fmaf_rn(v.z,v.z,s2); s3 = __fmaf_rn(v.w,v.w,s3);
            }
            ssb[bi*CK + tid] = __fadd_rn(__fadd_rn(s0,s1), __fadd_rn(s2,s3));
        }
    };

    loadB(0, 0);
    __syncthreads();

    // per-thread row state: L = rt*2 + half  (rows: wrow+rt*16+g, +8)
    float cthr[4];
    cthr[0] = cths[wrow + g];      cthr[1] = cths[wrow + g + 8];
    cthr[2] = cths[wrow + 16 + g]; cthr[3] = cths[wrow + 24 + g];
    float thr[4]  = {3.4e38f,3.4e38f,3.4e38f,3.4e38f};
    float rmin[4] = {3.4e38f,3.4e38f,3.4e38f,3.4e38f};
    int   cnt[4]  = {0,0,0,0};
    unsigned short cand[4*CAP];   // local mem (dynamic idx), rare access

    #define PUSH(dot, L, cth_, ss_, idx_) do{                         \
        float dv_ = __fmaf_rn((dot), -2.0f, __fadd_rn((cth_),(ss_))); \
        if (dv_ < thr[L]){                                            \
            if (cnt[L] < CAP) cand[(L)*CAP + cnt[L]] = (unsigned short)(idx_); \
            cnt[L]++;                                                 \
            if (dv_ < rmin[L]){ rmin[L] = dv_; thr[L] = __fadd_rn(dv_, EPS); } \
        } }while(0)

    #pragma unroll 1
    for (int c=0; c<NCK; c++){
        const int p = c & 1;
        if (c+1 < NCK) loadB((c+1)*CK, p^1);

        const uint32_t* Bp = sB + p*BUFU;
        const float*    sp = ssb + p*CK;
        const int cbase = c*CK;

        #pragma unroll 2
        for (int ct=0; ct<16; ct++){
            float C0[4] = {0.f,0.f,0.f,0.f};
            float C1[4] = {0.f,0.f,0.f,0.f};
            const uint32_t* bb = Bp + (ct*8 + g)*BSTRIDE + q;
            #pragma unroll
            for (int k=0; k<8; k++){
                uint32_t b0 = bb[k*8];
                uint32_t b1 = bb[k*8 + 4];
                mma8(C0, atf[0][k], b0, b1);
                mma8(C1, atf[1][k], b0, b1);
            }
            float2 ssv = *reinterpret_cast<const float2*>(sp + ct*8 + 2*q);
            int idx0 = cbase + ct*8 + 2*q;
            PUSH(C0[0], 0, cthr[0], ssv.x, idx0);
            PUSH(C0[1], 0, cthr[0], ssv.y, idx0+1);
            PUSH(C0[2], 1, cthr[1], ssv.x, idx0);
            PUSH(C0[3], 1, cthr[1], ssv.y, idx0+1);
            PUSH(C1[0], 2, cthr[2], ssv.x, idx0);
            PUSH(C1[1], 2, cthr[2], ssv.y, idx0+1);
            PUSH(C1[2], 3, cthr[3], ssv.x, idx0);
            PUSH(C1[3], 3, cthr[3], ssv.y, idx0+1);
        }
        __syncthreads();
    }
    #undef PUSH

    // ---- exact recheck + merge + fused outputs ----
    double lsum = 0.0;
    #pragma unroll 1
    for (int L=0; L<4; L++){
        const int rt = L >> 1, half = L & 1;
        const int rowl = wrow + rt*16 + half*8 + g;
        const size_t grow = rowbase + rowl;

        // load this row exactly (all 4 quad lanes load same row; L1 broadcast)
        float xv[64];
        const float4* xr = reinterpret_cast<const float4*>(x + grow*DIM);
        #pragma unroll
        for (int i=0;i<16;i++){
            float4 v = xr[i];
            xv[4*i+0]=v.x; xv[4*i+1]=v.y; xv[4*i+2]=v.z; xv[4*i+3]=v.w;
        }
        // exact ||x||^2 (sequential, reference order)
        float cth = 0.f;
        #pragma unroll
        for (int d=0; d<64; d++) cth = __fadd_rn(cth, __fmul_rn(xv[d], xv[d]));

        float minv = 3.402823466e38f; int mini = 0;
        if (cnt[L] <= CAP){
            for (int k2=0; k2<cnt[L]; k2++){
                int idx = (int)cand[L*CAP + k2];
                float d = exact_dist(w + (size_t)idx*DIM, xv, cth);
                if (d < minv){ minv = d; mini = idx; }
            }
        } else {  // overflow fallback: full exact scan
            for (int idx=0; idx<KC; idx++){
                float d = exact_dist(w + (size_t)idx*DIM, xv, cth);
                if (d < minv){ minv = d; mini = idx; }
            }
        }
        // merge across the 4 quad lanes (first-min tie-break on index)
        #pragma unroll
        for (int off=1; off<4; off<<=1){
            float od = __shfl_xor_sync(0xffffffffu, minv, off);
            int   oi = __shfl_xor_sync(0xffffffffu, mini, off);
            if (od < minv || (od == minv && oi < mini)){ minv = od; mini = oi; }
        }
        if (q == 0){
            out[1 + QELEMS + grow] = (float)mini;
            lsum += (double)minv;
            // fused straight-through output: x + (q - x).
            // out+1 is only 4B-aligned: write 3 scalars, 15 float4 (16B-aligned
            // from element 3: global float offset 64*grow+4), then 1 scalar.
            const float4* qw = reinterpret_cast<const float4*>(w + (size_t)mini*DIM);
            float stq[64];
            #pragma unroll
            for (int i=0;i<16;i++){
                float4 qv = qw[i];
                stq[4*i+0] = __fadd_rn(xv[4*i+0], __fsub_rn(qv.x, xv[4*i+0]));
                stq[4*i+1] = __fadd_rn(xv[4*i+1], __fsub_rn(qv.y, xv[4*i+1]));
                stq[4*i+2] = __fadd_rn(xv[4*i+2], __fsub_rn(qv.z, xv[4*i+2]));
                stq[4*i+3] = __fadd_rn(xv[4*i+3], __fsub_rn(qv.w, xv[4*i+3]));
            }
            float* og = out + 1 + grow*DIM;
            og[0] = stq[0]; og[1] = stq[1]; og[2] = stq[2];
            float4* ov = reinterpret_cast<float4*>(og + 3);
            #pragma unroll
            for (int i=0;i<15;i++){
                float4 r;
                r.x = stq[3+4*i]; r.y = stq[4+4*i];
                r.z = stq[5+4*i]; r.w = stq[6+4*i];
                ov[i] = r;
            }
            og[63] = stq[63];
        }
    }

    // ---- fp64 loss reduction ----
    #pragma unroll
    for (int o=16; o>0; o>>=1) lsum += __shfl_down_sync(0xffffffffu, lsum, o);
    if (lane == 0) sred[warp] = lsum;
    __syncthreads();
    if (tid == 0){
        atomicAdd(&g_loss_acc, sred[0] + sred[1] + sred[2] + sred[3]);
    }
}

__global__ void vq_final(float* __restrict__ out){
    double m = g_loss_acc / (double)QELEMS;
    out[0] = (float)(m + 0.25*m);
}

extern "C" void kernel_launch(void* const* d_in, const int* in_sizes, int n_in,
                              void* d_out, int out_size)
{
    const float* x  = (const float*)d_in[0];
    const float* wt = (const float*)d_in[1];
    float* out = (float*)d_out;

    cudaFuncSetAttribute(vq_main, cudaFuncAttributeMaxDynamicSharedMemorySize, SMEMSZ);

    vq_zero_kernel<<<1,1>>>();
    vq_main<<<NROWS/BROWS, BT, SMEMSZ>>>(x, wt, out);
    vq_final<<<1,1>>>(out);
}

// round 5
// speedup vs baseline: 6.2784x; 6.2784x over previous
#include <cuda_runtime.h>
#include <stdint.h>

#define NROWS   (64*2048)
#define DIM     64
#define KC      1024
#define QELEMS  (NROWS*DIM)

#define BT      128            // threads/block (4 warps)
#define BROWS   128            // rows per block (32 per warp)
#define CK      128            // codes per chunk
#define NCK     (KC/CK)        // 8
#define BSTRIDE 68             // padded floats per code row in smem (bank-conflict-free)
#define BUFU    (CK*BSTRIDE)   // uints per B buffer
#define CAP     12
#define EPS     2.0e-3f

// dynamic smem layout (uints/floats)
#define SM_B    0                       // uint sB[2][BUFU]  (tf32 bits)
#define SM_SS   (2*BUFU*4)              // float ss[2][CK]
#define SM_CTH  (SM_SS + 2*CK*4)        // float cth[BROWS]
#define SM_RED  (SM_CTH + BROWS*4)      // double sred[4]
#define SMEMSZ  (SM_RED + 64)

__device__ double g_loss_acc;

static __device__ __forceinline__ uint32_t tf32(float f){
    uint32_t r;
    asm("cvt.rna.tf32.f32 %0, %1;" : "=r"(r) : "f"(f));
    return r;
}
static __device__ __forceinline__ void mma8(float c[4], const uint32_t a[4],
                                            uint32_t b0, uint32_t b1){
    asm volatile("mma.sync.aligned.m16n8k8.row.col.f32.tf32.tf32.f32 "
        "{%0,%1,%2,%3}, {%4,%5,%6,%7}, {%8,%9}, {%0,%1,%2,%3};"
        : "+f"(c[0]),"+f"(c[1]),"+f"(c[2]),"+f"(c[3])
        : "r"(a[0]),"r"(a[1]),"r"(a[2]),"r"(a[3]), "r"(b0),"r"(b1));
}

__global__ void vq_zero_kernel(){ g_loss_acc = 0.0; }

// exact fp32 distance — replicates the round-1 (reference-matching) rounding order
static __device__ __forceinline__ float exact_dist(const float* __restrict__ wrow,
                                                   const float* __restrict__ xv, float cth){
    float ww[64];
    const float4* w4 = reinterpret_cast<const float4*>(wrow);
    #pragma unroll
    for (int i=0;i<16;i++){
        float4 v = w4[i];
        ww[4*i+0]=v.x; ww[4*i+1]=v.y; ww[4*i+2]=v.z; ww[4*i+3]=v.w;
    }
    float ss = 0.f;
    #pragma unroll
    for (int d=0; d<64; d++) ss = __fadd_rn(ss, __fmul_rn(ww[d], ww[d]));
    float s0=0.f, s1=0.f, s2=0.f, s3=0.f;
    #pragma unroll
    for (int d=0; d<64; d+=4){
        s0 = __fmaf_rn(xv[d+0], ww[d+0], s0);
        s1 = __fmaf_rn(xv[d+1], ww[d+1], s1);
        s2 = __fmaf_rn(xv[d+2], ww[d+2], s2);
        s3 = __fmaf_rn(xv[d+3], ww[d+3], s3);
    }
    float m = __fadd_rn(__fadd_rn(s0,s1), __fadd_rn(s2,s3));
    return __fsub_rn(__fadd_rn(cth, ss), __fmul_rn(2.0f, m));
}

__global__ __launch_bounds__(BT) void vq_main(const float* __restrict__ x,
                                              const float* __restrict__ w,
                                              float* __restrict__ out)
{
    extern __shared__ char smem[];
    uint32_t* sB   = reinterpret_cast<uint32_t*>(smem + SM_B);
    float*    ssb  = reinterpret_cast<float*>(smem + SM_SS);
    float*    cths = reinterpret_cast<float*>(smem + SM_CTH);
    double*   sred = reinterpret_cast<double*>(smem + SM_RED);

    const int tid  = threadIdx.x;
    const int warp = tid >> 5;
    const int lane = tid & 31;
    const int g    = lane >> 2;   // group id 0..7
    const int q    = lane & 3;    // thread-in-group 0..3
    const int blk  = blockIdx.x;
    const int wrow = warp * 32;   // warp's first row within block
    const size_t rowbase = (size_t)blk * BROWS;

    // ---- approx ||x||^2 per row (cooperative; recheck recomputes exactly) ----
    {
        const float4* xr = reinterpret_cast<const float4*>(x + (rowbase + tid)*DIM);
        float s0=0.f,s1=0.f,s2=0.f,s3=0.f;
        #pragma unroll
        for (int i=0;i<16;i++){
            float4 v = xr[i];
            s0 = __fmaf_rn(v.x,v.x,s0); s1 = __fmaf_rn(v.y,v.y,s1);
            s2 = __fmaf_rn(v.z,v.z,s2); s3 = __fmaf_rn(v.w,v.w,s3);
        }
        cths[tid] = __fadd_rn(__fadd_rn(s0,s1), __fadd_rn(s2,s3));
    }

    // ---- A fragments (2 row-tiles x 8 k-steps x 4 regs), tf32 ----
    uint32_t atf[2][8][4];
    {
        const float* xb = x + (rowbase + wrow)*DIM;
        #pragma unroll
        for (int rt=0; rt<2; rt++){
            #pragma unroll
            for (int k=0; k<8; k++){
                int r0 = rt*16 + g;
                int c0 = k*8 + q;
                atf[rt][k][0] = tf32(xb[(r0  )*DIM + c0    ]);
                atf[rt][k][1] = tf32(xb[(r0+8)*DIM + c0    ]);
                atf[rt][k][2] = tf32(xb[(r0  )*DIM + c0 + 4]);
                atf[rt][k][3] = tf32(xb[(r0+8)*DIM + c0 + 4]);
            }
        }
    }

    // ---- B chunk loader (codes [cb,cb+CK) -> buffer bi, tf32 + approx norms) ----
    auto loadB = [&](int cb, int bi){
        const float4* wg = reinterpret_cast<const float4*>(w + (size_t)cb*DIM);
        #pragma unroll
        for (int i=0;i<16;i++){
            int f4 = tid + i*BT;
            float4 v = wg[f4];
            int code = f4 >> 4;
            int dim  = (f4 & 15) * 4;
            uint32_t* dst = sB + bi*BUFU + code*BSTRIDE + dim;
            dst[0]=tf32(v.x); dst[1]=tf32(v.y); dst[2]=tf32(v.z); dst[3]=tf32(v.w);
        }
        {   // approx per-code norm (fp32)
            const float4* wr = reinterpret_cast<const float4*>(w + (size_t)(cb + tid)*DIM);
            float s0=0.f,s1=0.f,s2=0.f,s3=0.f;
            #pragma unroll
            for (int i=0;i<16;i++){
                float4 v = wr[i];
                s0 = __fmaf_rn(v.x,v.x,s0); s1 = __fmaf_rn(v.y,v.y,s1);
                s2 = __fmaf_rn(v.z,v.z,s2); s3 = __fmaf_rn(v.w,v.w,s3);
            }
            ssb[bi*CK + tid] = __fadd_rn(__fadd_rn(s0,s1), __fadd_rn(s2,s3));
        }
    };

    loadB(0, 0);
    __syncthreads();

    // per-thread row state: L = rt*2 + half  (rows: wrow+rt*16+g, +8)
    float cthr[4];
    cthr[0] = cths[wrow + g];      cthr[1] = cths[wrow + g + 8];
    cthr[2] = cths[wrow + 16 + g]; cthr[3] = cths[wrow + 24 + g];
    float thr[4]  = {3.4e38f,3.4e38f,3.4e38f,3.4e38f};
    float rmin[4] = {3.4e38f,3.4e38f,3.4e38f,3.4e38f};
    int   cnt[4]  = {0,0,0,0};
    bool  ovf[4]  = {false,false,false,false};
    unsigned short candI[4*CAP];   // local mem, rarely touched
    float          candD[4*CAP];

    // Push with threshold + compaction: buffer holds only candidates still
    // within EPS of the *current* min, so overflow is statistically impossible.
    #define PUSH(dot, L, cth_, ss_, idx_) do{                         \
        float dv_ = __fmaf_rn((dot), -2.0f, __fadd_rn((cth_),(ss_))); \
        if (dv_ < thr[L]){                                            \
            if (dv_ < rmin[L]){ rmin[L] = dv_; thr[L] = __fadd_rn(dv_, EPS); } \
            if (cnt[L] == CAP){                                       \
                int m_ = 0;                                           \
                for (int t2_=0; t2_<CAP; t2_++){                      \
                    float dvv_ = candD[(L)*CAP + t2_];                \
                    if (dvv_ < thr[L]){                               \
                        candD[(L)*CAP + m_] = dvv_;                   \
                        candI[(L)*CAP + m_] = candI[(L)*CAP + t2_];   \
                        m_++;                                         \
                    }                                                 \
                }                                                     \
                cnt[L] = m_;                                          \
            }                                                         \
            if (cnt[L] < CAP){                                        \
                candI[(L)*CAP + cnt[L]] = (unsigned short)(idx_);     \
                candD[(L)*CAP + cnt[L]] = dv_;                        \
                cnt[L]++;                                             \
            } else ovf[L] = true;                                     \
        } }while(0)

    #pragma unroll 1
    for (int c=0; c<NCK; c++){
        const int p = c & 1;
        if (c+1 < NCK) loadB((c+1)*CK, p^1);

        const uint32_t* Bp = sB + p*BUFU;
        const float*    sp = ssb + p*CK;
        const int cbase = c*CK;

        #pragma unroll 2
        for (int ct=0; ct<16; ct++){
            float C0[4] = {0.f,0.f,0.f,0.f};
            float C1[4] = {0.f,0.f,0.f,0.f};
            const uint32_t* bb = Bp + (ct*8 + g)*BSTRIDE + q;
            #pragma unroll
            for (int k=0; k<8; k++){
                uint32_t b0 = bb[k*8];
                uint32_t b1 = bb[k*8 + 4];
                mma8(C0, atf[0][k], b0, b1);
                mma8(C1, atf[1][k], b0, b1);
            }
            float2 ssv = *reinterpret_cast<const float2*>(sp + ct*8 + 2*q);
            int idx0 = cbase + ct*8 + 2*q;
            PUSH(C0[0], 0, cthr[0], ssv.x, idx0);
            PUSH(C0[1], 0, cthr[0], ssv.y, idx0+1);
            PUSH(C0[2], 1, cthr[1], ssv.x, idx0);
            PUSH(C0[3], 1, cthr[1], ssv.y, idx0+1);
            PUSH(C1[0], 2, cthr[2], ssv.x, idx0);
            PUSH(C1[1], 2, cthr[2], ssv.y, idx0+1);
            PUSH(C1[2], 3, cthr[3], ssv.x, idx0);
            PUSH(C1[3], 3, cthr[3], ssv.y, idx0+1);
        }
        __syncthreads();
    }
    #undef PUSH

    // ---- exact recheck + merge + fused outputs ----
    double lsum = 0.0;
    #pragma unroll 1
    for (int L=0; L<4; L++){
        const int rt = L >> 1, half = L & 1;
        const int rowl = wrow + rt*16 + half*8 + g;
        const size_t grow = rowbase + rowl;

        float xv[64];
        const float4* xr = reinterpret_cast<const float4*>(x + grow*DIM);
        #pragma unroll
        for (int i=0;i<16;i++){
            float4 v = xr[i];
            xv[4*i+0]=v.x; xv[4*i+1]=v.y; xv[4*i+2]=v.z; xv[4*i+3]=v.w;
        }
        // exact ||x||^2 (sequential, reference order)
        float cth = 0.f;
        #pragma unroll
        for (int d=0; d<64; d++) cth = __fadd_rn(cth, __fmul_rn(xv[d], xv[d]));

        float minv = 3.402823466e38f; int mini = 0;
        if (!ovf[L]){
            // candidates are in ascending code order; only those within the
            // final window matter
            for (int k2=0; k2<cnt[L]; k2++){
                if (candD[L*CAP + k2] < thr[L]){
                    int idx = (int)candI[L*CAP + k2];
                    float d = exact_dist(w + (size_t)idx*DIM, xv, cth);
                    if (d < minv){ minv = d; mini = idx; }
                }
            }
        } else {  // unreachable in practice: full exact scan
            for (int idx=0; idx<KC; idx++){
                float d = exact_dist(w + (size_t)idx*DIM, xv, cth);
                if (d < minv){ minv = d; mini = idx; }
            }
        }
        // merge across the 4 quad lanes (first-min tie-break on index)
        #pragma unroll
        for (int off=1; off<4; off<<=1){
            float od = __shfl_xor_sync(0xffffffffu, minv, off);
            int   oi = __shfl_xor_sync(0xffffffffu, mini, off);
            if (od < minv || (od == minv && oi < mini)){ minv = od; mini = oi; }
        }
        if (q == 0){
            out[1 + QELEMS + grow] = (float)mini;
            lsum += (double)minv;
            // fused straight-through output: x + (q - x); out+1 only 4B-aligned
            const float4* qw = reinterpret_cast<const float4*>(w + (size_t)mini*DIM);
            float stq[64];
            #pragma unroll
            for (int i=0;i<16;i++){
                float4 qv = qw[i];
                stq[4*i+0] = __fadd_rn(xv[4*i+0], __fsub_rn(qv.x, xv[4*i+0]));
                stq[4*i+1] = __fadd_rn(xv[4*i+1], __fsub_rn(qv.y, xv[4*i+1]));
                stq[4*i+2] = __fadd_rn(xv[4*i+2], __fsub_rn(qv.z, xv[4*i+2]));
                stq[4*i+3] = __fadd_rn(xv[4*i+3], __fsub_rn(qv.w, xv[4*i+3]));
            }
            float* og = out + 1 + grow*DIM;
            og[0] = stq[0]; og[1] = stq[1]; og[2] = stq[2];
            float4* ov = reinterpret_cast<float4*>(og + 3);
            #pragma unroll
            for (int i=0;i<15;i++){
                float4 r;
                r.x = stq[3+4*i]; r.y = stq[4+4*i];
                r.z = stq[5+4*i]; r.w = stq[6+4*i];
                ov[i] = r;
            }
            og[63] = stq[63];
        }
    }

    // ---- fp64 loss reduction ----
    #pragma unroll
    for (int o=16; o>0; o>>=1) lsum += __shfl_down_sync(0xffffffffu, lsum, o);
    if (lane == 0) sred[warp] = lsum;
    __syncthreads();
    if (tid == 0){
        atomicAdd(&g_loss_acc, sred[0] + sred[1] + sred[2] + sred[3]);
    }
}

__global__ void vq_final(float* __restrict__ out){
    double m = g_loss_acc / (double)QELEMS;
    out[0] = (float)(m + 0.25*m);
}

extern "C" void kernel_launch(void* const* d_in, const int* in_sizes, int n_in,
                              void* d_out, int out_size)
{
    const float* x  = (const float*)d_in[0];
    const float* wt = (const float*)d_in[1];
    float* out = (float*)d_out;

    cudaFuncSetAttribute(vq_main, cudaFuncAttributeMaxDynamicSharedMemorySize, SMEMSZ);

    vq_zero_kernel<<<1,1>>>();
    vq_main<<<NROWS/BROWS, BT, SMEMSZ>>>(x, wt, out);
    vq_final<<<1,1>>>(out);
}